// round 6
// baseline (speedup 1.0000x reference)
#include <cuda_runtime.h>

// Shapes (fixed per reference): B=1024, C=200, L=3, DIM=512, SEQ=C+1=201
#define B_    1024
#define C_    200
#define DIM_  512
#define SEQ_  201
#define BT    8        // batch rows per block
#define NS    8        // seq positions per block (26 blocks cover 201, tail-guarded)
#define GRX   ((SEQ_ + NS - 1) / NS)   // 26

// out[b,0,d]   = cls[d] + pe[0,d]
// out[b,c+1,d] = x[b,clamp(c-1)]*W[c,0,d] + x[b,c]*W[c,1,d] + x[b,clamp(c+1)]*W[c,2,d] + pe[c+1,d]

__device__ __forceinline__ void stcs4(float4* p, float4 v) {
    // streaming store: evict-first in L2, drain straight to DRAM
    asm volatile("st.global.cs.v4.f32 [%0], {%1, %2, %3, %4};"
                 :: "l"(p), "f"(v.x), "f"(v.y), "f"(v.z), "f"(v.w) : "memory");
}

// Issue the 24 independent x loads for seq position s (c = s-1; s>=1).
__device__ __forceinline__ void load_x(const float* __restrict__ x, int b_base, int s,
                                       float* xa, float* xm, float* xz) {
    const int c   = s - 1;
    const int cm1 = (c > 0)      ? c - 1 : 0;
    const int cp1 = (c < C_ - 1) ? c + 1 : C_ - 1;
    #pragma unroll
    for (int i = 0; i < BT; i++) {
        const size_t row = (size_t)(b_base + i) * C_;
        xa[i] = __ldg(x + row + cm1);
        xm[i] = __ldg(x + row + c);
        xz[i] = __ldg(x + row + cp1);
    }
}

__global__ __launch_bounds__(128, 6)
void GSE_band_proj_kernel(const float* __restrict__ x,
                          const float* __restrict__ W,
                          const float* __restrict__ cls,
                          const float* __restrict__ pe,
                          float* __restrict__ out) {
    const int d4     = threadIdx.x;          // 0..127 (float4 index into DIM=512)
    const int b_base = blockIdx.y * BT;
    const int s0     = blockIdx.x * NS;      // first seq position of this block
    const int s_end  = (s0 + NS < SEQ_) ? s0 + NS : SEQ_;

    int s = s0;

    // cls row (only block x==0 sees s==0)
    if (s == 0) {
        const float4 cv = reinterpret_cast<const float4*>(cls)[d4];
        const float4 pv = reinterpret_cast<const float4*>(pe)[d4];
        float4 r;
        r.x = cv.x + pv.x;  r.y = cv.y + pv.y;
        r.z = cv.z + pv.z;  r.w = cv.w + pv.w;
        #pragma unroll
        for (int i = 0; i < BT; i++) {
            const size_t b = (size_t)(b_base + i);
            stcs4(reinterpret_cast<float4*>(out + (b * SEQ_) * DIM_) + d4, r);
        }
        s = 1;
    }

    if (s >= s_end) return;

    // ---- software pipeline: prefetch x for step s, then each loop body
    // prefetches s+1 before draining s's stores ----
    float xa0[BT], xm0[BT], xz0[BT];   // current
    float xa1[BT], xm1[BT], xz1[BT];   // next
    load_x(x, b_base, s, xa0, xm0, xz0);

    for (; s < s_end; s++) {
        const int c = s - 1;

        // W/pe loads for current step (L2-resident, shared by 128 CTAs)
        const float4 w0 = reinterpret_cast<const float4*>(W + ((size_t)c * 3 + 0) * DIM_)[d4];
        const float4 w1 = reinterpret_cast<const float4*>(W + ((size_t)c * 3 + 1) * DIM_)[d4];
        const float4 w2 = reinterpret_cast<const float4*>(W + ((size_t)c * 3 + 2) * DIM_)[d4];
        const float4 pv = reinterpret_cast<const float4*>(pe + (size_t)(c + 1) * DIM_)[d4];

        // prefetch NEXT step's x while this step's FMAs+stores run
        const bool have_next = (s + 1 < s_end);
        if (have_next)
            load_x(x, b_base, s + 1, xa1, xm1, xz1);

        #pragma unroll
        for (int i = 0; i < BT; i++) {
            const size_t b = (size_t)(b_base + i);
            float4 r;
            r.x = fmaf(xa0[i], w0.x, fmaf(xm0[i], w1.x, fmaf(xz0[i], w2.x, pv.x)));
            r.y = fmaf(xa0[i], w0.y, fmaf(xm0[i], w1.y, fmaf(xz0[i], w2.y, pv.y)));
            r.z = fmaf(xa0[i], w0.z, fmaf(xm0[i], w1.z, fmaf(xz0[i], w2.z, pv.z)));
            r.w = fmaf(xa0[i], w0.w, fmaf(xm0[i], w1.w, fmaf(xz0[i], w2.w, pv.w)));
            stcs4(reinterpret_cast<float4*>(out + (b * SEQ_ + s) * DIM_) + d4, r);
        }

        if (have_next) {
            #pragma unroll
            for (int i = 0; i < BT; i++) {
                xa0[i] = xa1[i];
                xm0[i] = xm1[i];
                xz0[i] = xz1[i];
            }
        }
    }
}

extern "C" void kernel_launch(void* const* d_in, const int* in_sizes, int n_in,
                              void* d_out, int out_size) {
    const float* x   = (const float*)d_in[0];
    const float* W   = (const float*)d_in[1];
    const float* cls = (const float*)d_in[2];
    const float* pe  = (const float*)d_in[3];
    float* out = (float*)d_out;

    dim3 grid(GRX, B_ / BT, 1);    // 26 x 128 blocks
    dim3 block(DIM_ / 4, 1, 1);    // 128 threads, one float4 each
    GSE_band_proj_kernel<<<grid, block>>>(x, W, cls, pe, out);
}

// round 7
// speedup vs baseline: 1.5219x; 1.5219x over previous
#include <cuda_runtime.h>

// Shapes (fixed per reference): B=1024, C=200, L=3, DIM=512, SEQ=C+1=201
#define B_    1024
#define C_    200
#define DIM_  512
#define SEQ_  201
#define BT    4        // batch rows per block (halved vs R4 to cut reg pressure)
#define NS    3        // seq positions per block (201 = 67 * 3)

// out[b,0,d]   = cls[d] + pe[0,d]
// out[b,c+1,d] = x[b,clamp(c-1)]*W[c,0,d] + x[b,c]*W[c,1,d] + x[b,clamp(c+1)]*W[c,2,d] + pe[c+1,d]

__device__ __forceinline__ void stcs4(float4* p, float4 v) {
    // streaming store: evict-first in L2, drain straight to DRAM
    asm volatile("st.global.cs.v4.f32 [%0], {%1, %2, %3, %4};"
                 :: "l"(p), "f"(v.x), "f"(v.y), "f"(v.z), "f"(v.w) : "memory");
}

__global__ __launch_bounds__(128, 10)
void GSE_band_proj_kernel(const float* __restrict__ x,
                          const float* __restrict__ W,
                          const float* __restrict__ cls,
                          const float* __restrict__ pe,
                          float* __restrict__ out) {
    const int d4     = threadIdx.x;          // 0..127 (float4 index into DIM=512)
    const int b_base = blockIdx.y * BT;
    const int s0     = blockIdx.x * NS;      // first of NS consecutive seq positions

    #pragma unroll
    for (int js = 0; js < NS; js++) {
        const int s = s0 + js;               // 0..200

        if (s == 0) {
            const float4 cv = reinterpret_cast<const float4*>(cls)[d4];
            const float4 pv = reinterpret_cast<const float4*>(pe)[d4];
            float4 r;
            r.x = cv.x + pv.x;  r.y = cv.y + pv.y;
            r.z = cv.z + pv.z;  r.w = cv.w + pv.w;
            #pragma unroll
            for (int i = 0; i < BT; i++) {
                const size_t b = (size_t)(b_base + i);
                stcs4(reinterpret_cast<float4*>(out + (b * SEQ_) * DIM_) + d4, r);
            }
            continue;
        }

        const int c   = s - 1;                       // 0..199
        const int cm1 = (c > 0)      ? c - 1 : 0;    // edge-replicate pad
        const int cp1 = (c < C_ - 1) ? c + 1 : C_ - 1;

        // Independent LDGs up front; the store loop never waits on a load.
        // Stores from the previous js iteration drain while these are in flight.
        float xa[BT], xm[BT], xz[BT];
        #pragma unroll
        for (int i = 0; i < BT; i++) {
            const size_t row = (size_t)(b_base + i) * C_;
            xa[i] = __ldg(x + row + cm1);
            xm[i] = __ldg(x + row + c);
            xz[i] = __ldg(x + row + cp1);
        }

        const float4 w0 = reinterpret_cast<const float4*>(W + ((size_t)c * 3 + 0) * DIM_)[d4];
        const float4 w1 = reinterpret_cast<const float4*>(W + ((size_t)c * 3 + 1) * DIM_)[d4];
        const float4 w2 = reinterpret_cast<const float4*>(W + ((size_t)c * 3 + 2) * DIM_)[d4];
        const float4 pv = reinterpret_cast<const float4*>(pe + (size_t)(c + 1) * DIM_)[d4];

        #pragma unroll
        for (int i = 0; i < BT; i++) {
            const size_t b = (size_t)(b_base + i);
            float4 r;
            r.x = fmaf(xa[i], w0.x, fmaf(xm[i], w1.x, fmaf(xz[i], w2.x, pv.x)));
            r.y = fmaf(xa[i], w0.y, fmaf(xm[i], w1.y, fmaf(xz[i], w2.y, pv.y)));
            r.z = fmaf(xa[i], w0.z, fmaf(xm[i], w1.z, fmaf(xz[i], w2.z, pv.z)));
            r.w = fmaf(xa[i], w0.w, fmaf(xm[i], w1.w, fmaf(xz[i], w2.w, pv.w)));
            stcs4(reinterpret_cast<float4*>(out + (b * SEQ_ + s) * DIM_) + d4, r);
        }
    }
}

extern "C" void kernel_launch(void* const* d_in, const int* in_sizes, int n_in,
                              void* d_out, int out_size) {
    const float* x   = (const float*)d_in[0];
    const float* W   = (const float*)d_in[1];
    const float* cls = (const float*)d_in[2];
    const float* pe  = (const float*)d_in[3];
    float* out = (float*)d_out;

    dim3 grid(SEQ_ / NS, B_ / BT, 1);   // 67 x 256 blocks = 17152 CTAs
    dim3 block(DIM_ / 4, 1, 1);         // 128 threads, one float4 each
    GSE_band_proj_kernel<<<grid, block>>>(x, W, cls, pe, out);
}